// round 16
// baseline (speedup 1.0000x reference)
#include <cuda_runtime.h>
#include <cuda_fp16.h>
#include <math.h>
#include <stdint.h>

#define Bsz 2
#define Nn 2048
#define Cc 256
#define COOR 3
#define Hh 8
#define Dd 64
#define Ee 192   // Dd * COOR
#define DI 512   // Hh * Dd
#define BH 16    // Bsz * Hh
#define Jb 6144  // per-batch j dim = Nn*3

// flash smem: Q hi/lo persistent (64 rows) + 2-stage (K hi 16 rows | V hi | V lo)
#define F_LDQ 200          // Q/K rows: 192 + 8 pad halves (400B)
#define F_LDV 24           // V rows: 16 + 8 pad halves (48B)
#define F_OQH 0
#define F_OQL 25600
#define F_KV0 51200
#define F_STG 24832        // KH 6400 | VH 9216 | VL 9216
#define F_SMEM (F_KV0 + 2 * F_STG)   // 100864  -> 2 CTAs/SM via smem fit
#define F_THREADS 128

// gemm smem: 2 stages of (W 128x64 + X 192x64) hi/lo
#define G_LDW 72
#define G_STG 92160        // WH 18432 | WL 18432 | XH 27648 | XL 27648
#define G_SMEM (2 * G_STG) // 184320

// ---------------- scratch (device globals; no runtime allocation) ----------
__device__ __half g_qh[BH * Nn * Ee];
__device__ __half g_ql[BH * Nn * Ee];
__device__ __half g_kh[BH * Nn * Ee];
__device__ __half g_kl[BH * Nn * Ee];
__device__ __half g_vh[BH * Ee * Nn];   // [bh][e][n]
__device__ __half g_vl[BH * Ee * Nn];
__device__ float  g_ao[BH * Nn * Ee];
__device__ __half g_wh[3 * DI * Cc];    // stacked Wq,Wk,Wv [1536][256]
__device__ __half g_wl[3 * DI * Cc];
__device__ __half g_woh[Cc * DI];       // Wo [256][512]
__device__ __half g_wol[Cc * DI];
__device__ __half g_xth[Bsz * Jb * Cc]; // xT [b][j][i]
__device__ __half g_xtl[Bsz * Jb * Cc];
__device__ __half g_aoth[Bsz * Jb * DI];// aoT [b][j][h*64+d]
__device__ __half g_aotl[Bsz * Jb * DI];

// ---------------- helpers ---------------------------------------------------
__device__ __forceinline__ uint32_t s2u(const void* p) {
    uint32_t a;
    asm("{ .reg .u64 t; cvta.to.shared.u64 t, %1; cvt.u32.u64 %0, t; }"
        : "=r"(a) : "l"(p));
    return a;
}
__device__ __forceinline__ void ldm4(uint32_t& r0, uint32_t& r1, uint32_t& r2,
                                     uint32_t& r3, uint32_t addr) {
    asm volatile("ldmatrix.sync.aligned.m8n8.x4.shared.b16 {%0,%1,%2,%3}, [%4];"
                 : "=r"(r0), "=r"(r1), "=r"(r2), "=r"(r3) : "r"(addr));
}
__device__ __forceinline__ void mma16816(float* c, const uint32_t* a, const uint32_t* b) {
    asm volatile(
        "mma.sync.aligned.m16n8k16.row.col.f32.f16.f16.f32 "
        "{%0,%1,%2,%3},{%4,%5,%6,%7},{%8,%9},{%0,%1,%2,%3};"
        : "+f"(c[0]), "+f"(c[1]), "+f"(c[2]), "+f"(c[3])
        : "r"(a[0]), "r"(a[1]), "r"(a[2]), "r"(a[3]), "r"(b[0]), "r"(b[1]));
}
__device__ __forceinline__ void cpa16(uint32_t dst, const void* src) {
    asm volatile("cp.async.cg.shared.global [%0], [%1], 16;"
                 :: "r"(dst), "l"(src));
}
__device__ __forceinline__ void cpa_commit() {
    asm volatile("cp.async.commit_group;");
}
__device__ __forceinline__ void cpa_wait0() {
    asm volatile("cp.async.wait_group 0;");
}
__device__ __forceinline__ void cpa_wait1() {
    asm volatile("cp.async.wait_group 1;");
}
__device__ __forceinline__ void split_f16(float x, __half& h, __half& l) {
    h = __float2half(x);
    l = __float2half(x - __half2float(h));
}
__device__ __forceinline__ uint32_t pack_f16x2(float a, float b) {
    __half2 p = __halves2half2(__float2half(a), __float2half(b));
    return *(uint32_t*)&p;
}

// ---------------------------------------------------------------------------
// prep kernels
// ---------------------------------------------------------------------------
__global__ __launch_bounds__(256)
void split_arr(const float* __restrict__ src, __half* __restrict__ h,
               __half* __restrict__ l, int n)
{
    int i = blockIdx.x * 1024 + threadIdx.x;
    #pragma unroll
    for (int s = 0; s < 4; ++s, i += 256)
        if (i < n) {
            __half hi, lo;
            split_f16(src[i], hi, lo);
            h[i] = hi; l[i] = lo;
        }
}

__global__ __launch_bounds__(256)
void prep_x(const float* __restrict__ x,
            __half* __restrict__ xh, __half* __restrict__ xl)
{
    __shared__ float sm[768];
    const int blk = blockIdx.x;
    const int b = blk >> 11, n = blk & 2047;
    const int tid = threadIdx.x;
    const long base = (long)blk * 768;
    #pragma unroll
    for (int s = 0; s < 3; ++s)
        sm[tid + s * 256] = x[base + tid + s * 256];
    __syncthreads();
    #pragma unroll
    for (int s = 0; s < 3; ++s) {
        int c = s, i = tid;
        __half hi, lo;
        split_f16(sm[i * 3 + c], hi, lo);
        long dst = ((long)b * Jb + n * 3 + c) * Cc + i;
        xh[dst] = hi; xl[dst] = lo;
    }
}

__global__ __launch_bounds__(256)
void prep_ao(const float* __restrict__ ao,
             __half* __restrict__ h, __half* __restrict__ l)
{
    __shared__ float sm[4][192];
    const int R0 = blockIdx.x * 4;
    const int tid = threadIdx.x;
    {
        int t = tid;
        for (int s = 0; s < 3; ++s, t += 256)
            sm[t / 192][t % 192] = ao[(long)R0 * 192 + t];
    }
    __syncthreads();
    {
        int t = tid;
        for (int s = 0; s < 3; ++s, t += 256) {
            int row = t / 192, idx = t % 192;
            int c = idx >> 6, d = idx & 63;
            int g = R0 + row;
            int bh = g >> 11, n = g & 2047;
            int b = bh >> 3, hh = bh & 7;
            __half hi, lo;
            split_f16(sm[row][d * 3 + c], hi, lo);
            long dst = ((long)b * Jb + n * 3 + c) * DI + hh * 64 + d;
            h[dst] = hi; l[dst] = lo;
        }
    }
}

// ---------------------------------------------------------------------------
// GEMM mainloop, 2-stage pipelined, fp16 3-product split.
// ---------------------------------------------------------------------------
__device__ __forceinline__ void gemm_issue(
    uint32_t sb, int tid, int stage, int i0,
    const __half* __restrict__ wh, const __half* __restrict__ wl,
    const __half* __restrict__ xh, const __half* __restrict__ xl,
    int ktot)
{
    const uint32_t b0 = sb + stage * G_STG;
    #pragma unroll
    for (int s = 0; s < 4; ++s) {
        int l = tid + s * 256;
        int row = l >> 3, sg = l & 7;
        uint32_t doff = (uint32_t)(row * G_LDW + sg * 8) * 2;
        long g = (long)row * ktot + i0 + sg * 8;
        cpa16(b0 + doff, wh + g);
        cpa16(b0 + 18432 + doff, wl + g);
    }
    #pragma unroll
    for (int s = 0; s < 6; ++s) {
        int l = tid + s * 256;
        int row = l >> 3, sg = l & 7;
        uint32_t doff = (uint32_t)(row * G_LDW + sg * 8) * 2;
        long g = (long)row * ktot + i0 + sg * 8;
        cpa16(b0 + 36864 + doff, xh + g);
        cpa16(b0 + 64512 + doff, xl + g);
    }
}

__device__ __forceinline__ void gemm_main(
    uint32_t sb, int tid,
    const __half* __restrict__ wh, const __half* __restrict__ wl,
    const __half* __restrict__ xh, const __half* __restrict__ xl,
    int ktot, float acc[4][6][4])
{
    const int lane = tid & 31, w = tid >> 5;
    const int wm = w >> 2, wn = w & 3;
    const int lrow = lane & 15, lc8 = (lane >> 4) << 3;
    const int nch = ktot >> 6;

    gemm_issue(sb, tid, 0, 0, wh, wl, xh, xl, ktot);
    cpa_commit();

    for (int ch = 0; ch < nch; ++ch) {
        if (ch + 1 < nch) {
            gemm_issue(sb, tid, (ch + 1) & 1, (ch + 1) * 64, wh, wl, xh, xl, ktot);
            cpa_commit();
            cpa_wait1();
        } else {
            cpa_wait0();
        }
        __syncthreads();

        const uint32_t b0 = sb + (ch & 1) * G_STG;
        #pragma unroll
        for (int ks = 0; ks < 4; ++ks) {
            const int kcol = ks * 16 + lc8;
            uint32_t ah_[4][4], al_[4][4];
            #pragma unroll
            for (int mt = 0; mt < 4; ++mt) {
                uint32_t r = (uint32_t)((wm * 64 + mt * 16 + lrow) * G_LDW + kcol) * 2;
                ldm4(ah_[mt][0], ah_[mt][1], ah_[mt][2], ah_[mt][3], b0 + r);
                ldm4(al_[mt][0], al_[mt][1], al_[mt][2], al_[mt][3], b0 + 18432 + r);
            }
            uint32_t bh_[6][2], bl_[6][2];
            #pragma unroll
            for (int g = 0; g < 3; ++g) {
                uint32_t r = (uint32_t)((wn * 48 + g * 16 + lrow) * G_LDW + kcol) * 2;
                uint32_t b0r, b1r, b2r, b3r;
                ldm4(b0r, b1r, b2r, b3r, b0 + 36864 + r);
                bh_[2*g][0] = b0r; bh_[2*g][1] = b2r;
                bh_[2*g+1][0] = b1r; bh_[2*g+1][1] = b3r;
                ldm4(b0r, b1r, b2r, b3r, b0 + 64512 + r);
                bl_[2*g][0] = b0r; bl_[2*g][1] = b2r;
                bl_[2*g+1][0] = b1r; bl_[2*g+1][1] = b3r;
            }
            #pragma unroll
            for (int mt = 0; mt < 4; ++mt)
                #pragma unroll
                for (int nt = 0; nt < 6; ++nt) {
                    mma16816(acc[mt][nt], ah_[mt], bh_[nt]);
                    mma16816(acc[mt][nt], ah_[mt], bl_[nt]);
                    mma16816(acc[mt][nt], al_[mt], bh_[nt]);
                }
        }
        __syncthreads();
    }
}

// ---------------------------------------------------------------------------
// QKV projection GEMM
// ---------------------------------------------------------------------------
__global__ __launch_bounds__(256, 1)
void qkv_mm(const __half* __restrict__ wh, const __half* __restrict__ wl,
            const __half* __restrict__ xh, const __half* __restrict__ xl,
            __half* __restrict__ qh, __half* __restrict__ ql,
            __half* __restrict__ kh, __half* __restrict__ kl,
            __half* __restrict__ vh, __half* __restrict__ vl)
{
    extern __shared__ __align__(16) char sm[];
    const uint32_t sb = s2u(sm);
    const int tid = threadIdx.x, lane = tid & 31, w = tid >> 5;
    const int wm = w >> 2, wn = w & 3;
    const int jt = blockIdx.x, ot = blockIdx.y;
    const int b = jt >> 5, o0 = ot * 128;
    const int m = o0 >> 9;

    float acc[4][6][4] = {};
    gemm_main(sb, tid,
              wh + (long)o0 * Cc, wl + (long)o0 * Cc,
              xh + ((long)b * Jb + (jt & 31) * 192) * Cc,
              xl + ((long)b * Jb + (jt & 31) * 192) * Cc,
              Cc, acc);

    __half* oh = (m == 0) ? qh : (m == 1) ? kh : vh;
    __half* ol = (m == 0) ? ql : (m == 1) ? kl : vl;

    #pragma unroll
    for (int mt = 0; mt < 4; ++mt)
        #pragma unroll
        for (int nt = 0; nt < 6; ++nt)
            #pragma unroll
            for (int e = 0; e < 4; ++e) {
                int rloc = wm * 64 + mt * 16 + (lane >> 2) + ((e >> 1) << 3);
                int cloc = wn * 48 + nt * 8 + (lane & 3) * 2 + (e & 1);
                int o_in = (o0 & 511) + rloc;
                int hh = o_in >> 6, d = o_in & 63;
                int bh = b * 8 + hh;
                int jb = (jt & 31) * 192 + cloc;
                int n = jb / 3, c = jb - 3 * n;
                __half hi, lo;
                split_f16(acc[mt][nt][e], hi, lo);
                long idx;
                if (m < 2) idx = ((long)bh * Nn + n) * Ee + d * 3 + c;
                else       idx = ((long)bh * Ee + d * 3 + c) * Nn + n;
                oh[idx] = hi; ol[idx] = lo;
            }
}

// ---------------------------------------------------------------------------
// Output projection GEMM
// ---------------------------------------------------------------------------
__global__ __launch_bounds__(256, 1)
void out_mm(const __half* __restrict__ wh, const __half* __restrict__ wl,
            const __half* __restrict__ xh, const __half* __restrict__ xl,
            float* __restrict__ y)
{
    extern __shared__ __align__(16) char sm[];
    const uint32_t sb = s2u(sm);
    const int tid = threadIdx.x, lane = tid & 31, w = tid >> 5;
    const int wm = w >> 2, wn = w & 3;
    const int jt = blockIdx.x, ot = blockIdx.y;
    const int b = jt >> 5, o0 = ot * 128;

    float acc[4][6][4] = {};
    gemm_main(sb, tid,
              wh + (long)o0 * DI, wl + (long)o0 * DI,
              xh + ((long)b * Jb + (jt & 31) * 192) * DI,
              xl + ((long)b * Jb + (jt & 31) * 192) * DI,
              DI, acc);

    #pragma unroll
    for (int mt = 0; mt < 4; ++mt)
        #pragma unroll
        for (int nt = 0; nt < 6; ++nt)
            #pragma unroll
            for (int e = 0; e < 4; ++e) {
                int rloc = wm * 64 + mt * 16 + (lane >> 2) + ((e >> 1) << 3);
                int cloc = wn * 48 + nt * 8 + (lane & 3) * 2 + (e & 1);
                int o = o0 + rloc;
                int jb = (jt & 31) * 192 + cloc;
                int n = jb / 3, c = jb - 3 * n;
                y[((long)(b * Nn + n) * Cc + o) * 3 + c] = acc[mt][nt][e];
            }
}

// ---------------------------------------------------------------------------
// Fused flash attention: 128 threads, i-tile 64, j-chunk 16, 2 CTAs/SM (smem fit).
// QK: S = (Qh + Ql) * Kh ; AV: O += Pf16 * (Vh + Vl)
// ---------------------------------------------------------------------------
__device__ __forceinline__ void flash_issue(
    uint32_t sb, int tid, int jc, int stage,
    const __half* __restrict__ Kh,
    const __half* __restrict__ Vh, const __half* __restrict__ Vl)
{
    const uint32_t kb = sb + F_KV0 + stage * F_STG;
    #pragma unroll
    for (int it = 0; it < 3; ++it) {
        int s = tid + it * F_THREADS;
        int row = s / 24, seg = s - row * 24;          // K: 16 rows x 24 segs
        uint32_t doff = (uint32_t)(row * F_LDQ + seg * 8) * 2;
        long g = (long)(jc + row) * Ee + seg * 8;
        cpa16(kb + doff, Kh + g);
    }
    #pragma unroll
    for (int it = 0; it < 3; ++it) {
        int s = tid + it * F_THREADS;
        int row = s >> 1, seg = s & 1;                 // V: 192 rows x 2 segs
        uint32_t doff = (uint32_t)(row * F_LDV + seg * 8) * 2;
        long g = (long)row * Nn + jc + seg * 8;
        cpa16(kb + 6400 + doff, Vh + g);
        cpa16(kb + 15616 + doff, Vl + g);
    }
}

__global__ __launch_bounds__(F_THREADS)
void vn_flash(const __half* __restrict__ qh, const __half* __restrict__ ql,
              const __half* __restrict__ kh,
              const __half* __restrict__ vh, const __half* __restrict__ vl,
              float* __restrict__ ao, float scale)
{
    extern __shared__ __align__(16) char sm[];
    const uint32_t sb = s2u(sm);
    const int tid = threadIdx.x, lane = tid & 31, w = tid >> 5;
    const int i0 = blockIdx.x * 64, bh = blockIdx.y;
    const int lrow = lane & 15, lc8 = (lane >> 4) << 3;

    const __half* Kh = kh + (long)bh * Nn * Ee;
    const __half* Vh = vh + (long)bh * Ee * Nn;
    const __half* Vl = vl + (long)bh * Ee * Nn;

    // stage Q (64 x 192 hi/lo) + first K/V chunk, one commit group
    {
        const __half* Qh = qh + ((long)bh * Nn + i0) * Ee;
        const __half* Ql = ql + ((long)bh * Nn + i0) * Ee;
        for (int s = tid; s < 64 * 24; s += F_THREADS) {
            int row = s / 24, seg = s - row * 24;
            uint32_t doff = (uint32_t)(row * F_LDQ + seg * 8) * 2;
            long g = (long)row * Ee + seg * 8;
            cpa16(sb + F_OQH + doff, Qh + g);
            cpa16(sb + F_OQL + doff, Ql + g);
        }
    }
    flash_issue(sb, tid, 0, 0, Kh, Vh, Vl);
    cpa_commit();

    float O[24][4];
    #pragma unroll
    for (int i = 0; i < 24; ++i) { O[i][0]=0.f; O[i][1]=0.f; O[i][2]=0.f; O[i][3]=0.f; }
    float m0 = -1e30f, m1 = -1e30f, l0 = 0.f, l1 = 0.f;

    for (int ch = 0; ch < 128; ++ch) {
        if (ch < 127) {
            flash_issue(sb, tid, (ch + 1) * 16, (ch + 1) & 1, Kh, Vh, Vl);
            cpa_commit();
            cpa_wait1();
        } else {
            cpa_wait0();
        }
        __syncthreads();

        const uint32_t kb = sb + F_KV0 + (ch & 1) * F_STG;

        // ---- S = q k^T  (16 rows x 16 cols per warp; 2-product) ----
        float S[2][4];
        S[0][0]=0.f; S[0][1]=0.f; S[0][2]=0.f; S[0][3]=0.f;
        S[1][0]=0.f; S[1][1]=0.f; S[1][2]=0.f; S[1][3]=0.f;
        #pragma unroll
        for (int ks = 0; ks < 12; ++ks) {
            const int kcol = ks * 16 + lc8;
            uint32_t qah[4], qal[4];
            uint32_t r = (uint32_t)((w * 16 + lrow) * F_LDQ + kcol) * 2;
            ldm4(qah[0], qah[1], qah[2], qah[3], sb + F_OQH + r);
            ldm4(qal[0], qal[1], qal[2], qal[3], sb + F_OQL + r);
            uint32_t rb = (uint32_t)(lrow * F_LDQ + kcol) * 2;
            uint32_t b0, b1, b2, b3;
            ldm4(b0, b1, b2, b3, kb + rb);
            uint32_t bh0[2] = {b0, b2}, bh1[2] = {b1, b3};
            mma16816(S[0], qah, bh0);
            mma16816(S[0], qal, bh0);
            mma16816(S[1], qah, bh1);
            mma16816(S[1], qal, bh1);
        }

        // ---- online softmax ----
        float pm0, pm1;
        {
            float a = fmaxf(fmaxf(S[0][0], S[0][1]), fmaxf(S[1][0], S[1][1]));
            float b = fmaxf(fmaxf(S[0][2], S[0][3]), fmaxf(S[1][2], S[1][3]));
            pm0 = a * scale; pm1 = b * scale;
        }
        pm0 = fmaxf(pm0, __shfl_xor_sync(0xffffffffu, pm0, 1));
        pm0 = fmaxf(pm0, __shfl_xor_sync(0xffffffffu, pm0, 2));
        pm1 = fmaxf(pm1, __shfl_xor_sync(0xffffffffu, pm1, 1));
        pm1 = fmaxf(pm1, __shfl_xor_sync(0xffffffffu, pm1, 2));
        const float nm0 = fmaxf(m0, pm0), nm1 = fmaxf(m1, pm1);
        const float a0 = __expf(m0 - nm0), a1 = __expf(m1 - nm1);
        float rs0 = 0.f, rs1 = 0.f;
        #pragma unroll
        for (int nt = 0; nt < 2; ++nt) {
            S[nt][0] = __expf(S[nt][0] * scale - nm0);
            S[nt][1] = __expf(S[nt][1] * scale - nm0);
            S[nt][2] = __expf(S[nt][2] * scale - nm1);
            S[nt][3] = __expf(S[nt][3] * scale - nm1);
            rs0 += S[nt][0] + S[nt][1];
            rs1 += S[nt][2] + S[nt][3];
        }
        rs0 += __shfl_xor_sync(0xffffffffu, rs0, 1);
        rs0 += __shfl_xor_sync(0xffffffffu, rs0, 2);
        rs1 += __shfl_xor_sync(0xffffffffu, rs1, 1);
        rs1 += __shfl_xor_sync(0xffffffffu, rs1, 2);
        l0 = l0 * a0 + rs0;
        l1 = l1 * a1 + rs1;
        m0 = nm0; m1 = nm1;
        #pragma unroll
        for (int nt = 0; nt < 24; ++nt) {
            O[nt][0] *= a0; O[nt][1] *= a0; O[nt][2] *= a1; O[nt][3] *= a1;
        }

        // ---- pack P single fp16 (C-frag -> A-frag identity) ----
        uint32_t pa[4];
        pa[0] = pack_f16x2(S[0][0], S[0][1]);
        pa[1] = pack_f16x2(S[0][2], S[0][3]);
        pa[2] = pack_f16x2(S[1][0], S[1][1]);
        pa[3] = pack_f16x2(S[1][2], S[1][3]);

        // ---- O += P @ (Vh + Vl) ----
        #pragma unroll
        for (int gg = 0; gg < 12; ++gg) {
            uint32_t rb = (uint32_t)((gg * 16 + lrow) * F_LDV + lc8) * 2;
            uint32_t b0, b1, b2, b3;
            ldm4(b0, b1, b2, b3, kb + 6400 + rb);
            uint32_t vh0[2] = {b0, b2}, vh1[2] = {b1, b3};
            ldm4(b0, b1, b2, b3, kb + 15616 + rb);
            uint32_t vl0[2] = {b0, b2}, vl1[2] = {b1, b3};
            mma16816(O[2*gg],   pa, vh0);
            mma16816(O[2*gg],   pa, vl0);
            mma16816(O[2*gg+1], pa, vh1);
            mma16816(O[2*gg+1], pa, vl1);
        }
        __syncthreads();
    }

    // ---- epilogue ----
    const float inv0 = 1.f / l0, inv1 = 1.f / l1;
    const int rowg = i0 + w * 16 + (lane >> 2);
    const long base = ((long)bh * Nn + rowg) * Ee;
    #pragma unroll
    for (int nt = 0; nt < 24; ++nt) {
        int col = nt * 8 + (lane & 3) * 2;
        *(float2*)(ao + base + col) =
            make_float2(O[nt][0] * inv0, O[nt][1] * inv0);
        *(float2*)(ao + base + 8L * Ee + col) =
            make_float2(O[nt][2] * inv1, O[nt][3] * inv1);
    }
}

// ---------------------------------------------------------------------------
extern "C" void kernel_launch(void* const* d_in, const int* in_sizes, int n_in,
                              void* d_out, int out_size)
{
    const float* x  = (const float*)d_in[0];
    const float* Wq = (const float*)d_in[1];
    const float* Wk = (const float*)d_in[2];
    const float* Wv = (const float*)d_in[3];
    const float* Wo = (const float*)d_in[4];
    float* y = (float*)d_out;

    __half *qh, *ql, *kh, *kl, *vh, *vl;
    __half *wh, *wl, *woh, *wol, *xth, *xtl, *aoth, *aotl;
    float *ao;
    cudaGetSymbolAddress((void**)&qh,   g_qh);
    cudaGetSymbolAddress((void**)&ql,   g_ql);
    cudaGetSymbolAddress((void**)&kh,   g_kh);
    cudaGetSymbolAddress((void**)&kl,   g_kl);
    cudaGetSymbolAddress((void**)&vh,   g_vh);
    cudaGetSymbolAddress((void**)&vl,   g_vl);
    cudaGetSymbolAddress((void**)&ao,   g_ao);
    cudaGetSymbolAddress((void**)&wh,   g_wh);
    cudaGetSymbolAddress((void**)&wl,   g_wl);
    cudaGetSymbolAddress((void**)&woh,  g_woh);
    cudaGetSymbolAddress((void**)&wol,  g_wol);
    cudaGetSymbolAddress((void**)&xth,  g_xth);
    cudaGetSymbolAddress((void**)&xtl,  g_xtl);
    cudaGetSymbolAddress((void**)&aoth, g_aoth);
    cudaGetSymbolAddress((void**)&aotl, g_aotl);

    cudaFuncSetAttribute(vn_flash, cudaFuncAttributeMaxDynamicSharedMemorySize, F_SMEM);
    cudaFuncSetAttribute(qkv_mm,   cudaFuncAttributeMaxDynamicSharedMemorySize, G_SMEM);
    cudaFuncSetAttribute(out_mm,   cudaFuncAttributeMaxDynamicSharedMemorySize, G_SMEM);

    dim3 blk(256);

    const int WN = DI * Cc;
    split_arr<<<(WN + 1023) / 1024, blk>>>(Wq, wh, wl, WN);
    split_arr<<<(WN + 1023) / 1024, blk>>>(Wk, wh + WN, wl + WN, WN);
    split_arr<<<(WN + 1023) / 1024, blk>>>(Wv, wh + 2 * WN, wl + 2 * WN, WN);
    split_arr<<<(WN + 1023) / 1024, blk>>>(Wo, woh, wol, WN);
    prep_x<<<Bsz * Nn, blk>>>(x, xth, xtl);

    qkv_mm<<<dim3(64, 12), blk, G_SMEM>>>(wh, wl, xth, xtl,
                                          qh, ql, kh, kl, vh, vl);

    const float scale = 1.0f / sqrtf((float)Ee);
    vn_flash<<<dim3(Nn / 64, BH), dim3(F_THREADS), F_SMEM>>>(qh, ql, kh, vh, vl, ao, scale);

    prep_ao<<<BH * Nn / 4, blk>>>(ao, aoth, aotl);
    out_mm<<<dim3(64, 2), blk, G_SMEM>>>(woh, wol, aoth, aotl, y);
}

// round 17
// speedup vs baseline: 1.2850x; 1.2850x over previous
#include <cuda_runtime.h>
#include <cuda_fp16.h>
#include <math.h>
#include <stdint.h>

#define Bsz 2
#define Nn 2048
#define Cc 256
#define COOR 3
#define Hh 8
#define Dd 64
#define Ee 192   // Dd * COOR
#define DI 512   // Hh * Dd
#define BH 16    // Bsz * Hh
#define Jb 6144  // per-batch j dim = Nn*3

// flash smem: Q hi/lo persistent + 2-stage (K hi | V hi | V lo)  [R13 proven]
#define F_LDQ 200          // Q/K rows: 192 + 8 pad halves (400B)
#define F_LDV 40           // V rows: 32 + 8 pad halves (80B)
#define F_OQH 0
#define F_OQL 51200
#define F_KV0 102400
#define F_STG 43520        // KH 12800 | VH 15360 | VL 15360
#define F_SMEM (F_KV0 + 2 * F_STG)   // 189440

// gemm smem: 2 stages of (W-hi 128x64 + X hi/lo 192x64)
#define G_LDW 72
#define G_STG 73728        // WH 18432 | XH 27648 | XL 27648
#define G_SMEM (2 * G_STG) // 147456

// ---------------- scratch (device globals; no runtime allocation) ----------
__device__ __half g_qh[BH * Nn * Ee];
__device__ __half g_ql[BH * Nn * Ee];
__device__ __half g_kh[BH * Nn * Ee];
__device__ __half g_kl[BH * Nn * Ee];
__device__ __half g_vh[BH * Ee * Nn];   // [bh][e][n]
__device__ __half g_vl[BH * Ee * Nn];
__device__ float  g_ao[BH * Nn * Ee];
__device__ __half g_wh[3 * DI * Cc];    // stacked Wq,Wk,Wv hi [1536][256]
__device__ __half g_woh[Cc * DI];       // Wo hi [256][512]
__device__ __half g_xth[Bsz * Jb * Cc]; // xT [b][j][i]
__device__ __half g_xtl[Bsz * Jb * Cc];
__device__ __half g_aoth[Bsz * Jb * DI];// aoT [b][j][h*64+d]
__device__ __half g_aotl[Bsz * Jb * DI];

// ---------------- helpers ---------------------------------------------------
__device__ __forceinline__ uint32_t s2u(const void* p) {
    uint32_t a;
    asm("{ .reg .u64 t; cvta.to.shared.u64 t, %1; cvt.u32.u64 %0, t; }"
        : "=r"(a) : "l"(p));
    return a;
}
__device__ __forceinline__ void ldm4(uint32_t& r0, uint32_t& r1, uint32_t& r2,
                                     uint32_t& r3, uint32_t addr) {
    asm volatile("ldmatrix.sync.aligned.m8n8.x4.shared.b16 {%0,%1,%2,%3}, [%4];"
                 : "=r"(r0), "=r"(r1), "=r"(r2), "=r"(r3) : "r"(addr));
}
__device__ __forceinline__ void mma16816(float* c, const uint32_t* a, const uint32_t* b) {
    asm volatile(
        "mma.sync.aligned.m16n8k16.row.col.f32.f16.f16.f32 "
        "{%0,%1,%2,%3},{%4,%5,%6,%7},{%8,%9},{%0,%1,%2,%3};"
        : "+f"(c[0]), "+f"(c[1]), "+f"(c[2]), "+f"(c[3])
        : "r"(a[0]), "r"(a[1]), "r"(a[2]), "r"(a[3]), "r"(b[0]), "r"(b[1]));
}
__device__ __forceinline__ void cpa16(uint32_t dst, const void* src) {
    asm volatile("cp.async.cg.shared.global [%0], [%1], 16;"
                 :: "r"(dst), "l"(src));
}
__device__ __forceinline__ void cpa_commit() {
    asm volatile("cp.async.commit_group;");
}
__device__ __forceinline__ void cpa_wait0() {
    asm volatile("cp.async.wait_group 0;");
}
__device__ __forceinline__ void cpa_wait1() {
    asm volatile("cp.async.wait_group 1;");
}
__device__ __forceinline__ void split_f16(float x, __half& h, __half& l) {
    h = __float2half(x);
    l = __float2half(x - __half2float(h));
}
__device__ __forceinline__ uint32_t pack_f16x2(float a, float b) {
    __half2 p = __halves2half2(__float2half(a), __float2half(b));
    return *(uint32_t*)&p;
}

// ---------------------------------------------------------------------------
// prep kernels
// ---------------------------------------------------------------------------
// fused weight convert (hi only): grid (128, 4), 131072 elems per weight
__global__ __launch_bounds__(256)
void cvt_w(const float* __restrict__ wq, const float* __restrict__ wk,
           const float* __restrict__ wv, const float* __restrict__ wo,
           __half* __restrict__ wh, __half* __restrict__ woh)
{
    const int which = blockIdx.y;
    const float* src = (which == 0) ? wq : (which == 1) ? wk
                     : (which == 2) ? wv : wo;
    __half* dst = (which < 3) ? (wh + which * (DI * Cc)) : woh;
    int i = blockIdx.x * 1024 + threadIdx.x;
    #pragma unroll
    for (int s = 0; s < 4; ++s, i += 256)
        dst[i] = __float2half(src[i]);
}

__global__ __launch_bounds__(256)
void prep_x(const float* __restrict__ x,
            __half* __restrict__ xh, __half* __restrict__ xl)
{
    __shared__ float sm[768];
    const int blk = blockIdx.x;
    const int b = blk >> 11, n = blk & 2047;
    const int tid = threadIdx.x;
    const long base = (long)blk * 768;
    #pragma unroll
    for (int s = 0; s < 3; ++s)
        sm[tid + s * 256] = x[base + tid + s * 256];
    __syncthreads();
    #pragma unroll
    for (int s = 0; s < 3; ++s) {
        int c = s, i = tid;
        __half hi, lo;
        split_f16(sm[i * 3 + c], hi, lo);
        long dst = ((long)b * Jb + n * 3 + c) * Cc + i;
        xh[dst] = hi; xl[dst] = lo;
    }
}

__global__ __launch_bounds__(256)
void prep_ao(const float* __restrict__ ao,
             __half* __restrict__ h, __half* __restrict__ l)
{
    __shared__ float sm[4][192];
    const int R0 = blockIdx.x * 4;
    const int tid = threadIdx.x;
    {
        int t = tid;
        for (int s = 0; s < 3; ++s, t += 256)
            sm[t / 192][t % 192] = ao[(long)R0 * 192 + t];
    }
    __syncthreads();
    {
        int t = tid;
        for (int s = 0; s < 3; ++s, t += 256) {
            int row = t / 192, idx = t % 192;
            int c = idx >> 6, d = idx & 63;
            int g = R0 + row;
            int bh = g >> 11, n = g & 2047;
            int b = bh >> 3, hh = bh & 7;
            __half hi, lo;
            split_f16(sm[row][d * 3 + c], hi, lo);
            long dst = ((long)b * Jb + n * 3 + c) * DI + hh * 64 + d;
            h[dst] = hi; l[dst] = lo;
        }
    }
}

// ---------------------------------------------------------------------------
// GEMM mainloop, 2-stage pipelined, 2-product: C = Wh*(Xh + Xl).
// ---------------------------------------------------------------------------
__device__ __forceinline__ void gemm_issue(
    uint32_t sb, int tid, int stage, int i0,
    const __half* __restrict__ wh,
    const __half* __restrict__ xh, const __half* __restrict__ xl,
    int ktot)
{
    const uint32_t b0 = sb + stage * G_STG;
    #pragma unroll
    for (int s = 0; s < 4; ++s) {
        int l = tid + s * 256;
        int row = l >> 3, sg = l & 7;
        uint32_t doff = (uint32_t)(row * G_LDW + sg * 8) * 2;
        long g = (long)row * ktot + i0 + sg * 8;
        cpa16(b0 + doff, wh + g);
    }
    #pragma unroll
    for (int s = 0; s < 6; ++s) {
        int l = tid + s * 256;
        int row = l >> 3, sg = l & 7;
        uint32_t doff = (uint32_t)(row * G_LDW + sg * 8) * 2;
        long g = (long)row * ktot + i0 + sg * 8;
        cpa16(b0 + 18432 + doff, xh + g);
        cpa16(b0 + 46080 + doff, xl + g);
    }
}

__device__ __forceinline__ void gemm_main(
    uint32_t sb, int tid,
    const __half* __restrict__ wh,
    const __half* __restrict__ xh, const __half* __restrict__ xl,
    int ktot, float acc[4][6][4])
{
    const int lane = tid & 31, w = tid >> 5;
    const int wm = w >> 2, wn = w & 3;
    const int lrow = lane & 15, lc8 = (lane >> 4) << 3;
    const int nch = ktot >> 6;

    gemm_issue(sb, tid, 0, 0, wh, xh, xl, ktot);
    cpa_commit();

    for (int ch = 0; ch < nch; ++ch) {
        if (ch + 1 < nch) {
            gemm_issue(sb, tid, (ch + 1) & 1, (ch + 1) * 64, wh, xh, xl, ktot);
            cpa_commit();
            cpa_wait1();
        } else {
            cpa_wait0();
        }
        __syncthreads();

        const uint32_t b0 = sb + (ch & 1) * G_STG;
        #pragma unroll
        for (int ks = 0; ks < 4; ++ks) {
            const int kcol = ks * 16 + lc8;
            uint32_t ah_[4][4];
            #pragma unroll
            for (int mt = 0; mt < 4; ++mt) {
                uint32_t r = (uint32_t)((wm * 64 + mt * 16 + lrow) * G_LDW + kcol) * 2;
                ldm4(ah_[mt][0], ah_[mt][1], ah_[mt][2], ah_[mt][3], b0 + r);
            }
            uint32_t bh_[6][2], bl_[6][2];
            #pragma unroll
            for (int g = 0; g < 3; ++g) {
                uint32_t r = (uint32_t)((wn * 48 + g * 16 + lrow) * G_LDW + kcol) * 2;
                uint32_t b0r, b1r, b2r, b3r;
                ldm4(b0r, b1r, b2r, b3r, b0 + 18432 + r);
                bh_[2*g][0] = b0r; bh_[2*g][1] = b2r;
                bh_[2*g+1][0] = b1r; bh_[2*g+1][1] = b3r;
                ldm4(b0r, b1r, b2r, b3r, b0 + 46080 + r);
                bl_[2*g][0] = b0r; bl_[2*g][1] = b2r;
                bl_[2*g+1][0] = b1r; bl_[2*g+1][1] = b3r;
            }
            #pragma unroll
            for (int mt = 0; mt < 4; ++mt)
                #pragma unroll
                for (int nt = 0; nt < 6; ++nt) {
                    mma16816(acc[mt][nt], ah_[mt], bh_[nt]);
                    mma16816(acc[mt][nt], ah_[mt], bl_[nt]);
                }
        }
        __syncthreads();
    }
}

// ---------------------------------------------------------------------------
// QKV projection GEMM
// ---------------------------------------------------------------------------
__global__ __launch_bounds__(256, 1)
void qkv_mm(const __half* __restrict__ wh,
            const __half* __restrict__ xh, const __half* __restrict__ xl,
            __half* __restrict__ qh, __half* __restrict__ ql,
            __half* __restrict__ kh, __half* __restrict__ kl,
            __half* __restrict__ vh, __half* __restrict__ vl)
{
    extern __shared__ __align__(16) char sm[];
    const uint32_t sb = s2u(sm);
    const int tid = threadIdx.x, lane = tid & 31, w = tid >> 5;
    const int wm = w >> 2, wn = w & 3;
    const int jt = blockIdx.x, ot = blockIdx.y;
    const int b = jt >> 5, o0 = ot * 128;
    const int m = o0 >> 9;

    float acc[4][6][4] = {};
    gemm_main(sb, tid,
              wh + (long)o0 * Cc,
              xh + ((long)b * Jb + (jt & 31) * 192) * Cc,
              xl + ((long)b * Jb + (jt & 31) * 192) * Cc,
              Cc, acc);

    __half* oh = (m == 0) ? qh : (m == 1) ? kh : vh;
    __half* ol = (m == 0) ? ql : (m == 1) ? kl : vl;

    #pragma unroll
    for (int mt = 0; mt < 4; ++mt)
        #pragma unroll
        for (int nt = 0; nt < 6; ++nt)
            #pragma unroll
            for (int e = 0; e < 4; ++e) {
                int rloc = wm * 64 + mt * 16 + (lane >> 2) + ((e >> 1) << 3);
                int cloc = wn * 48 + nt * 8 + (lane & 3) * 2 + (e & 1);
                int o_in = (o0 & 511) + rloc;
                int hh = o_in >> 6, d = o_in & 63;
                int bh = b * 8 + hh;
                int jb = (jt & 31) * 192 + cloc;
                int n = jb / 3, c = jb - 3 * n;
                __half hi, lo;
                split_f16(acc[mt][nt][e], hi, lo);
                long idx;
                if (m < 2) idx = ((long)bh * Nn + n) * Ee + d * 3 + c;
                else       idx = ((long)bh * Ee + d * 3 + c) * Nn + n;
                oh[idx] = hi; ol[idx] = lo;
            }
}

// ---------------------------------------------------------------------------
// Output projection GEMM
// ---------------------------------------------------------------------------
__global__ __launch_bounds__(256, 1)
void out_mm(const __half* __restrict__ wh,
            const __half* __restrict__ xh, const __half* __restrict__ xl,
            float* __restrict__ y)
{
    extern __shared__ __align__(16) char sm[];
    const uint32_t sb = s2u(sm);
    const int tid = threadIdx.x, lane = tid & 31, w = tid >> 5;
    const int wm = w >> 2, wn = w & 3;
    const int jt = blockIdx.x, ot = blockIdx.y;
    const int b = jt >> 5, o0 = ot * 128;

    float acc[4][6][4] = {};
    gemm_main(sb, tid,
              wh + (long)o0 * DI,
              xh + ((long)b * Jb + (jt & 31) * 192) * DI,
              xl + ((long)b * Jb + (jt & 31) * 192) * DI,
              DI, acc);

    #pragma unroll
    for (int mt = 0; mt < 4; ++mt)
        #pragma unroll
        for (int nt = 0; nt < 6; ++nt)
            #pragma unroll
            for (int e = 0; e < 4; ++e) {
                int rloc = wm * 64 + mt * 16 + (lane >> 2) + ((e >> 1) << 3);
                int cloc = wn * 48 + nt * 8 + (lane & 3) * 2 + (e & 1);
                int o = o0 + rloc;
                int jb = (jt & 31) * 192 + cloc;
                int n = jb / 3, c = jb - 3 * n;
                y[((long)(b * Nn + n) * Cc + o) * 3 + c] = acc[mt][nt][e];
            }
}

// ---------------------------------------------------------------------------
// Fused flash attention — R13 verbatim (proven 637 µs config).
// 256 threads, i-tile 128, j-chunk 32, 2-stage pipeline.
// QK: S = (Qh + Ql) * Kh ; AV: O += Pf16 * (Vh + Vl)
// ---------------------------------------------------------------------------
__device__ __forceinline__ void flash_issue(
    uint32_t sb, int tid, int jc, int stage,
    const __half* __restrict__ Kh,
    const __half* __restrict__ Vh, const __half* __restrict__ Vl)
{
    const uint32_t kb = sb + F_KV0 + stage * F_STG;
    #pragma unroll
    for (int it = 0; it < 3; ++it) {
        int s = tid + it * 256;
        int row = s / 24, seg = s - row * 24;          // K: 32 rows x 24 segs
        uint32_t doff = (uint32_t)(row * F_LDQ + seg * 8) * 2;
        long g = (long)(jc + row) * Ee + seg * 8;
        cpa16(kb + doff, Kh + g);
    }
    #pragma unroll
    for (int it = 0; it < 3; ++it) {
        int s = tid + it * 256;
        int row = s >> 2, seg = s & 3;                 // V: 192 rows x 4 segs
        uint32_t doff = (uint32_t)(row * F_LDV + seg * 8) * 2;
        long g = (long)row * Nn + jc + seg * 8;
        cpa16(kb + 12800 + doff, Vh + g);
        cpa16(kb + 28160 + doff, Vl + g);
    }
}

__global__ __launch_bounds__(256, 1)
void vn_flash(const __half* __restrict__ qh, const __half* __restrict__ ql,
              const __half* __restrict__ kh,
              const __half* __restrict__ vh, const __half* __restrict__ vl,
              float* __restrict__ ao, float scale)
{
    extern __shared__ __align__(16) char sm[];
    const uint32_t sb = s2u(sm);
    const int tid = threadIdx.x, lane = tid & 31, w = tid >> 5;
    const int i0 = blockIdx.x * 128, bh = blockIdx.y;
    const int lrow = lane & 15, lc8 = (lane >> 4) << 3;

    const __half* Kh = kh + (long)bh * Nn * Ee;
    const __half* Vh = vh + (long)bh * Ee * Nn;
    const __half* Vl = vl + (long)bh * Ee * Nn;

    {
        const __half* Qh = qh + ((long)bh * Nn + i0) * Ee;
        const __half* Ql = ql + ((long)bh * Nn + i0) * Ee;
        for (int s = tid; s < 128 * 24; s += 256) {
            int row = s / 24, seg = s - row * 24;
            uint32_t doff = (uint32_t)(row * F_LDQ + seg * 8) * 2;
            long g = (long)row * Ee + seg * 8;
            cpa16(sb + F_OQH + doff, Qh + g);
            cpa16(sb + F_OQL + doff, Ql + g);
        }
    }
    flash_issue(sb, tid, 0, 0, Kh, Vh, Vl);
    cpa_commit();

    float O[24][4];
    #pragma unroll
    for (int i = 0; i < 24; ++i) { O[i][0]=0.f; O[i][1]=0.f; O[i][2]=0.f; O[i][3]=0.f; }
    float m0 = -1e30f, m1 = -1e30f, l0 = 0.f, l1 = 0.f;

    for (int ch = 0; ch < 64; ++ch) {
        if (ch < 63) {
            flash_issue(sb, tid, (ch + 1) * 32, (ch + 1) & 1, Kh, Vh, Vl);
            cpa_commit();
            cpa_wait1();
        } else {
            cpa_wait0();
        }
        __syncthreads();

        const uint32_t kb = sb + F_KV0 + (ch & 1) * F_STG;

        float S[4][4];
        #pragma unroll
        for (int i = 0; i < 4; ++i) { S[i][0]=0.f; S[i][1]=0.f; S[i][2]=0.f; S[i][3]=0.f; }
        #pragma unroll
        for (int ks = 0; ks < 12; ++ks) {
            const int kcol = ks * 16 + lc8;
            uint32_t qah[4], qal[4];
            uint32_t r = (uint32_t)((w * 16 + lrow) * F_LDQ + kcol) * 2;
            ldm4(qah[0], qah[1], qah[2], qah[3], sb + F_OQH + r);
            ldm4(qal[0], qal[1], qal[2], qal[3], sb + F_OQL + r);
            #pragma unroll
            for (int g = 0; g < 2; ++g) {
                uint32_t rb = (uint32_t)((g * 16 + lrow) * F_LDQ + kcol) * 2;
                uint32_t b0, b1, b2, b3;
                ldm4(b0, b1, b2, b3, kb + rb);
                uint32_t bh0[2] = {b0, b2}, bh1[2] = {b1, b3};
                mma16816(S[2*g],   qah, bh0);
                mma16816(S[2*g],   qal, bh0);
                mma16816(S[2*g+1], qah, bh1);
                mma16816(S[2*g+1], qal, bh1);
            }
        }

        float pm0 = -1e30f, pm1 = -1e30f;
        #pragma unroll
        for (int nt = 0; nt < 4; ++nt) {
            S[nt][0] *= scale; S[nt][1] *= scale; S[nt][2] *= scale; S[nt][3] *= scale;
            pm0 = fmaxf(pm0, fmaxf(S[nt][0], S[nt][1]));
            pm1 = fmaxf(pm1, fmaxf(S[nt][2], S[nt][3]));
        }
        pm0 = fmaxf(pm0, __shfl_xor_sync(0xffffffffu, pm0, 1));
        pm0 = fmaxf(pm0, __shfl_xor_sync(0xffffffffu, pm0, 2));
        pm1 = fmaxf(pm1, __shfl_xor_sync(0xffffffffu, pm1, 1));
        pm1 = fmaxf(pm1, __shfl_xor_sync(0xffffffffu, pm1, 2));
        const float nm0 = fmaxf(m0, pm0), nm1 = fmaxf(m1, pm1);
        const float a0 = __expf(m0 - nm0), a1 = __expf(m1 - nm1);
        float rs0 = 0.f, rs1 = 0.f;
        #pragma unroll
        for (int nt = 0; nt < 4; ++nt) {
            S[nt][0] = __expf(S[nt][0] - nm0);
            S[nt][1] = __expf(S[nt][1] - nm0);
            S[nt][2] = __expf(S[nt][2] - nm1);
            S[nt][3] = __expf(S[nt][3] - nm1);
            rs0 += S[nt][0] + S[nt][1];
            rs1 += S[nt][2] + S[nt][3];
        }
        rs0 += __shfl_xor_sync(0xffffffffu, rs0, 1);
        rs0 += __shfl_xor_sync(0xffffffffu, rs0, 2);
        rs1 += __shfl_xor_sync(0xffffffffu, rs1, 1);
        rs1 += __shfl_xor_sync(0xffffffffu, rs1, 2);
        l0 = l0 * a0 + rs0;
        l1 = l1 * a1 + rs1;
        m0 = nm0; m1 = nm1;
        #pragma unroll
        for (int nt = 0; nt < 24; ++nt) {
            O[nt][0] *= a0; O[nt][1] *= a0; O[nt][2] *= a1; O[nt][3] *= a1;
        }

        uint32_t pa[2][4];
        #pragma unroll
        for (int ks = 0; ks < 2; ++ks) {
            const int e2 = 2 * ks, o2 = 2 * ks + 1;
            pa[ks][0] = pack_f16x2(S[e2][0], S[e2][1]);
            pa[ks][1] = pack_f16x2(S[e2][2], S[e2][3]);
            pa[ks][2] = pack_f16x2(S[o2][0], S[o2][1]);
            pa[ks][3] = pack_f16x2(S[o2][2], S[o2][3]);
        }

        #pragma unroll
        for (int ks = 0; ks < 2; ++ks) {
            const int kcol = ks * 16 + lc8;
            #pragma unroll
            for (int gg = 0; gg < 12; ++gg) {
                uint32_t rb = (uint32_t)((gg * 16 + lrow) * F_LDV + kcol) * 2;
                uint32_t b0, b1, b2, b3;
                ldm4(b0, b1, b2, b3, kb + 12800 + rb);
                uint32_t vh0[2] = {b0, b2}, vh1[2] = {b1, b3};
                ldm4(b0, b1, b2, b3, kb + 28160 + rb);
                uint32_t vl0[2] = {b0, b2}, vl1[2] = {b1, b3};
                mma16816(O[2*gg],   pa[ks], vh0);
                mma16816(O[2*gg],   pa[ks], vl0);
                mma16816(O[2*gg+1], pa[ks], vh1);
                mma16816(O[2*gg+1], pa[ks], vl1);
            }
        }
        __syncthreads();
    }

    const float inv0 = 1.f / l0, inv1 = 1.f / l1;
    const int rowg = i0 + w * 16 + (lane >> 2);
    const long base = ((long)bh * Nn + rowg) * Ee;
    #pragma unroll
    for (int nt = 0; nt < 24; ++nt) {
        int col = nt * 8 + (lane & 3) * 2;
        *(float2*)(ao + base + col) =
            make_float2(O[nt][0] * inv0, O[nt][1] * inv0);
        *(float2*)(ao + base + 8L * Ee + col) =
            make_float2(O[nt][2] * inv1, O[nt][3] * inv1);
    }
}

// ---------------------------------------------------------------------------
extern "C" void kernel_launch(void* const* d_in, const int* in_sizes, int n_in,
                              void* d_out, int out_size)
{
    const float* x  = (const float*)d_in[0];
    const float* Wq = (const float*)d_in[1];
    const float* Wk = (const float*)d_in[2];
    const float* Wv = (const float*)d_in[3];
    const float* Wo = (const float*)d_in[4];
    float* y = (float*)d_out;

    __half *qh, *ql, *kh, *kl, *vh, *vl;
    __half *wh, *woh, *xth, *xtl, *aoth, *aotl;
    float *ao;
    cudaGetSymbolAddress((void**)&qh,   g_qh);
    cudaGetSymbolAddress((void**)&ql,   g_ql);
    cudaGetSymbolAddress((void**)&kh,   g_kh);
    cudaGetSymbolAddress((void**)&kl,   g_kl);
    cudaGetSymbolAddress((void**)&vh,   g_vh);
    cudaGetSymbolAddress((void**)&vl,   g_vl);
    cudaGetSymbolAddress((void**)&ao,   g_ao);
    cudaGetSymbolAddress((void**)&wh,   g_wh);
    cudaGetSymbolAddress((void**)&woh,  g_woh);
    cudaGetSymbolAddress((void**)&xth,  g_xth);
    cudaGetSymbolAddress((void**)&xtl,  g_xtl);
    cudaGetSymbolAddress((void**)&aoth, g_aoth);
    cudaGetSymbolAddress((void**)&aotl, g_aotl);

    cudaFuncSetAttribute(vn_flash, cudaFuncAttributeMaxDynamicSharedMemorySize, F_SMEM);
    cudaFuncSetAttribute(qkv_mm,   cudaFuncAttributeMaxDynamicSharedMemorySize, G_SMEM);
    cudaFuncSetAttribute(out_mm,   cudaFuncAttributeMaxDynamicSharedMemorySize, G_SMEM);

    dim3 blk(256);

    // fused weight convert + input transpose/split
    cvt_w<<<dim3(128, 4), blk>>>(Wq, Wk, Wv, Wo, wh, woh);
    prep_x<<<Bsz * Nn, blk>>>(x, xth, xtl);

    qkv_mm<<<dim3(64, 12), blk, G_SMEM>>>(wh, xth, xtl,
                                          qh, ql, kh, kl, vh, vl);

    const float scale = 1.0f / sqrtf((float)Ee);
    vn_flash<<<dim3(Nn / 128, BH), blk, F_SMEM>>>(qh, ql, kh, vh, vl, ao, scale);

    prep_ao<<<BH * Nn / 4, blk>>>(ao, aoth, aotl);
    out_mm<<<dim3(64, 2), blk, G_SMEM>>>(woh, aoth, aotl, y);
}